// round 1
// baseline (speedup 1.0000x reference)
#include <cuda_runtime.h>
#include <math.h>

#define EMBED 2048
#define NEXP  64
#define TOPK  8
#define BM    128
#define BN    64
#define BK    32
#define SA    132   // padded stride for As[BK][SA] (conflict-free STS, aligned LDS.128)
#define SB    68    // padded stride for Bs[BK][SB] and score rows

__global__ __launch_bounds__(256, 2)
void router_kernel(const float* __restrict__ X,
                   const float* __restrict__ W,
                   const float* __restrict__ bias,
                   float* __restrict__ out,
                   int M, int write_idx)
{
    // 128*68 = 8704 floats (34 KB): holds A/B tiles during GEMM, score matrix in epilogue
    __shared__ float smem[BM * SB];
    float* As = smem;                // [BK][SA] = 4224 floats
    float* Bs = smem + BK * SA;      // [BK][SB] = 2176 floats  (total 6400 <= 8704)

    const int tid = threadIdx.x;
    const int m0  = blockIdx.x * BM;
    const int tx  = tid & 15;        // expert cols: tx*4 .. tx*4+3
    const int ty  = tid >> 4;        // token rows:  ty*8 .. ty*8+7

    // tile-load mapping: warp-uniform column group -> conflict-free transposed STS
    const int lr = tid & 31;         // row within pass
    const int lc = (tid >> 5) * 4;   // k-column group (0,4,...,28)

    float acc[8][4];
    #pragma unroll
    for (int i = 0; i < 8; i++)
        #pragma unroll
        for (int j = 0; j < 4; j++) acc[i][j] = 0.f;

    for (int k0 = 0; k0 < EMBED; k0 += BK) {
        __syncthreads();
        // A tile: 128 rows x 32 k, stored transposed As[k][m]
        #pragma unroll
        for (int p = 0; p < 4; p++) {
            int r = lr + p * 32;
            float4 v = *reinterpret_cast<const float4*>(
                X + (size_t)(m0 + r) * EMBED + k0 + lc);
            As[(lc + 0) * SA + r] = v.x;
            As[(lc + 1) * SA + r] = v.y;
            As[(lc + 2) * SA + r] = v.z;
            As[(lc + 3) * SA + r] = v.w;
        }
        // B tile: 64 expert rows x 32 k, stored transposed Bs[k][n]
        #pragma unroll
        for (int p = 0; p < 2; p++) {
            int r = lr + p * 32;
            float4 v = *reinterpret_cast<const float4*>(
                W + (size_t)r * EMBED + k0 + lc);
            Bs[(lc + 0) * SB + r] = v.x;
            Bs[(lc + 1) * SB + r] = v.y;
            Bs[(lc + 2) * SB + r] = v.z;
            Bs[(lc + 3) * SB + r] = v.w;
        }
        __syncthreads();

        #pragma unroll
        for (int kk = 0; kk < BK; kk++) {
            float4 a0 = *reinterpret_cast<const float4*>(As + kk * SA + ty * 8);
            float4 a1 = *reinterpret_cast<const float4*>(As + kk * SA + ty * 8 + 4);
            float4 b0 = *reinterpret_cast<const float4*>(Bs + kk * SB + tx * 4);
            float a[8] = {a0.x, a0.y, a0.z, a0.w, a1.x, a1.y, a1.z, a1.w};
            float b[4] = {b0.x, b0.y, b0.z, b0.w};
            #pragma unroll
            for (int i = 0; i < 8; i++)
                #pragma unroll
                for (int j = 0; j < 4; j++)
                    acc[i][j] = fmaf(a[i], b[j], acc[i][j]);
        }
    }

    // ---- epilogue: bias, stage scores to smem ----
    float4 bv = *reinterpret_cast<const float4*>(bias + tx * 4);
    __syncthreads();   // done reading As/Bs, smem reused for scores
    #pragma unroll
    for (int i = 0; i < 8; i++) {
        float4 v;
        v.x = acc[i][0] + bv.x;
        v.y = acc[i][1] + bv.y;
        v.z = acc[i][2] + bv.z;
        v.w = acc[i][3] + bv.w;
        *reinterpret_cast<float4*>(smem + (ty * 8 + i) * SB + tx * 4) = v;
    }
    __syncthreads();

    // ---- per-token top-8 + masked softmax (one thread per token) ----
    if (tid < BM) {
        const float* sc = smem + tid * SB;
        float vals[TOPK];
        int   idxs[TOPK];
        #pragma unroll
        for (int i = 0; i < TOPK; i++) { vals[i] = -INFINITY; idxs[i] = 0; }

        for (int j = 0; j < NEXP; j++) {
            float s = sc[j];
            if (s > vals[TOPK - 1]) {          // strict > : tie keeps lower index
                vals[TOPK - 1] = s;
                idxs[TOPK - 1] = j;
                #pragma unroll
                for (int q = TOPK - 1; q > 0; q--) {
                    if (vals[q] > vals[q - 1]) {
                        float tv = vals[q]; vals[q] = vals[q - 1]; vals[q - 1] = tv;
                        int   ti = idxs[q]; idxs[q] = idxs[q - 1]; idxs[q - 1] = ti;
                    }
                }
            }
        }

        // mask = topk scores at their slots, 0 elsewhere; softmax over all 64
        float mx   = fmaxf(vals[0], 0.f);
        float base = expf(-mx);
        float den  = (float)(NEXP - TOPK) * base;
        float ev[TOPK];
        #pragma unroll
        for (int i = 0; i < TOPK; i++) { ev[i] = expf(vals[i] - mx); den += ev[i]; }
        float inv = 1.f / den;
        float bz  = base * inv;

        float* orow = out + (size_t)(m0 + tid) * NEXP;
        #pragma unroll
        for (int j = 0; j < NEXP; j += 4) {
            float4 v; v.x = bz; v.y = bz; v.z = bz; v.w = bz;
            *reinterpret_cast<float4*>(orow + j) = v;
        }
        #pragma unroll
        for (int i = 0; i < TOPK; i++)
            orow[idxs[i]] = ev[i] * inv;       // same-thread overwrite: program order holds

        if (write_idx) {
            float* oi = out + (size_t)M * NEXP + (size_t)(m0 + tid) * TOPK;
            #pragma unroll
            for (int i = 0; i < TOPK; i++) oi[i] = (float)idxs[i];
        }
    }
}

extern "C" void kernel_launch(void* const* d_in, const int* in_sizes, int n_in,
                              void* d_out, int out_size) {
    const float* X = (const float*)d_in[0];
    const float* W = (const float*)d_in[1];
    const float* b = (const float*)d_in[2];
    int M = in_sizes[0] / EMBED;                       // 32768 tokens
    int write_idx = (out_size >= M * (NEXP + TOPK)) ? 1 : 0;
    router_kernel<<<M / BM, 256>>>(X, W, b, (float*)d_out, M, write_idx);
}